// round 3
// baseline (speedup 1.0000x reference)
#include <cuda_runtime.h>
#include <cstdint>

// Problem constants
#define BATCH 2
#define SEQ   2048
#define DIM   1024
#define NH    16
#define HD    64
#define MROWS (BATCH * SEQ)   // 4096

// Scratch (allocation-free rule: __device__ globals)
__device__ float g_Q[BATCH * NH * SEQ * HD];   // [b,h,s,hd]
__device__ float g_K[BATCH * NH * SEQ * HD];
__device__ float g_V[BATCH * NH * SEQ * HD];
__device__ float g_A[BATCH * SEQ * DIM];       // attention out, [b,s,h*hd]

// ---------------------------------------------------------------------------
// Helpers
// ---------------------------------------------------------------------------
__device__ __forceinline__ uint32_t smem_u32(const void* p) {
    uint32_t a;
    asm("{ .reg .u64 t; cvta.to.shared.u64 t, %1; cvt.u32.u64 %0, t; }" : "=r"(a) : "l"(p));
    return a;
}

#define CP_ASYNC16(dst, src) \
    asm volatile("cp.async.cg.shared.global [%0], [%1], 16;" :: "r"(dst), "l"(src))
#define CP_ASYNC_COMMIT() asm volatile("cp.async.commit_group;" ::: "memory")
#define CP_ASYNC_WAIT(n)  asm volatile("cp.async.wait_group %0;" :: "n"(n) : "memory")

__device__ __forceinline__ uint32_t f2tf32(float x) {
    uint32_t r;
    asm("cvt.rna.tf32.f32 %0, %1;" : "=r"(r) : "f"(x));
    return r;
}

#define MMA_TF32(d, av, bv)                                                   \
    asm volatile("mma.sync.aligned.m16n8k8.row.col.f32.tf32.tf32.f32 "        \
                 "{%0,%1,%2,%3}, {%4,%5,%6,%7}, {%8,%9}, {%0,%1,%2,%3};"      \
                 : "+f"((d)[0]), "+f"((d)[1]), "+f"((d)[2]), "+f"((d)[3])     \
                 : "r"((av)[0]), "r"((av)[1]), "r"((av)[2]), "r"((av)[3]),    \
                   "r"((bv)[0]), "r"((bv)[1]))

// ---------------------------------------------------------------------------
// tf32 mma.sync GEMM: C[m,n] = sum_k A[m,k]*W[n,k] + bias[n]
// CTA tile 128x256, BK=32. 8 warps: 2 (m) x 4 (n), each 64x64.
// Smem XOR-swizzled (phys_k = k ^ ((row&7)<<2)) -> conflict-free LDS + 16B
// contiguous cp.async chunks.
// ---------------------------------------------------------------------------
#define GBM 128
#define GBN 256
#define GBK 32
#define NKT (DIM / GBK)                 // 32
#define SA_BYTES (GBM * GBK * 4)        // 16384
#define SB_BYTES (GBN * GBK * 4)        // 32768
#define SM_GEMM_TOTAL (2 * (SA_BYTES + SB_BYTES))   // 98304

struct GemmArgs {
    const float* A;
    const float* W;
    const float* bias;
    float* C;
};

template <int SPLIT_HEADS>
__device__ __forceinline__ void gemm_body(const float* __restrict__ A,
                                          const float* __restrict__ W,
                                          const float* __restrict__ bias,
                                          float* __restrict__ C) {
    extern __shared__ char smem[];
    float* sAf = (float*)smem;                       // [2][128][32]
    float* sBf = (float*)(smem + 2 * SA_BYTES);      // [2][256][32]
    const uint32_t sA = smem_u32(smem);
    const uint32_t sB = sA + 2 * SA_BYTES;

    const int tid = threadIdx.x;
    const int lane = tid & 31;
    const int wid = tid >> 5;
    const int wm = wid & 1;          // 0..1
    const int wn = wid >> 1;         // 0..3
    const int g = lane >> 2;         // 0..7
    const int tig = lane & 3;        // 0..3
    const int m0 = blockIdx.y * GBM;
    const int n0 = blockIdx.x * GBN;

    float acc[4][8][4];
#pragma unroll
    for (int i = 0; i < 4; i++)
#pragma unroll
        for (int j = 0; j < 8; j++)
#pragma unroll
            for (int c = 0; c < 4; c++) acc[i][j][c] = 0.f;

    auto stage = [&](int kt, int buf) {
        const int k0 = kt * GBK;
#pragma unroll
        for (int t = 0; t < 4; t++) {
            int idx = tid + t * 256;
            int row = idx >> 3;
            int c = idx & 7;
            uint32_t dst = sA + buf * SA_BYTES + row * 128 + ((c ^ (row & 7)) << 4);
            CP_ASYNC16(dst, &A[(size_t)(m0 + row) * DIM + k0 + c * 4]);
        }
#pragma unroll
        for (int t = 0; t < 8; t++) {
            int idx = tid + t * 256;
            int row = idx >> 3;
            int c = idx & 7;
            uint32_t dst = sB + buf * SB_BYTES + row * 128 + ((c ^ (row & 7)) << 4);
            CP_ASYNC16(dst, &W[(size_t)(n0 + row) * DIM + k0 + c * 4]);
        }
    };

    stage(0, 0);
    CP_ASYNC_COMMIT();

    for (int kt = 0; kt < NKT; kt++) {
        if (kt + 1 < NKT) {
            stage(kt + 1, (kt + 1) & 1);
            CP_ASYNC_COMMIT();
            CP_ASYNC_WAIT(1);
        } else {
            CP_ASYNC_WAIT(0);
        }
        __syncthreads();

        const float* Ab = sAf + (kt & 1) * (SA_BYTES / 4);
        const float* Bb = sBf + (kt & 1) * (SB_BYTES / 4);
#pragma unroll
        for (int s = 0; s < 4; s++) {
            const int k1 = s * 8 + tig;
            const int k2 = k1 + 4;
            uint32_t a[4][4];
#pragma unroll
            for (int i = 0; i < 4; i++) {
                int r1 = wm * 64 + i * 16 + g;
                int r2 = r1 + 8;
                a[i][0] = f2tf32(Ab[r1 * 32 + (k1 ^ ((r1 & 7) << 2))]);
                a[i][1] = f2tf32(Ab[r2 * 32 + (k1 ^ ((r2 & 7) << 2))]);
                a[i][2] = f2tf32(Ab[r1 * 32 + (k2 ^ ((r1 & 7) << 2))]);
                a[i][3] = f2tf32(Ab[r2 * 32 + (k2 ^ ((r2 & 7) << 2))]);
            }
            uint32_t bf[8][2];
#pragma unroll
            for (int j = 0; j < 8; j++) {
                int rn = wn * 64 + j * 8 + g;
                bf[j][0] = f2tf32(Bb[rn * 32 + (k1 ^ ((rn & 7) << 2))]);
                bf[j][1] = f2tf32(Bb[rn * 32 + (k2 ^ ((rn & 7) << 2))]);
            }
#pragma unroll
            for (int i = 0; i < 4; i++)
#pragma unroll
                for (int j = 0; j < 8; j++) MMA_TF32(acc[i][j], a[i], bf[j]);
        }
        __syncthreads();
    }

    // Epilogue: direct stores with bias (float2 granularity)
#pragma unroll
    for (int i = 0; i < 4; i++) {
        const int m1 = m0 + wm * 64 + i * 16 + g;
        const int m2 = m1 + 8;
#pragma unroll
        for (int j = 0; j < 8; j++) {
            const int n = n0 + wn * 64 + j * 8 + tig * 2;
            const float2 bb = *(const float2*)&bias[n];
            float2 r1, r2;
            r1.x = acc[i][j][0] + bb.x;
            r1.y = acc[i][j][1] + bb.y;
            r2.x = acc[i][j][2] + bb.x;
            r2.y = acc[i][j][3] + bb.y;
            if (SPLIT_HEADS) {
                int h = n >> 6;
                int hd = n & (HD - 1);
                {
                    int b = m1 >> 11, sq = m1 & (SEQ - 1);
                    *(float2*)&C[((size_t)((b * NH + h) * SEQ + sq)) * HD + hd] = r1;
                }
                {
                    int b = m2 >> 11, sq = m2 & (SEQ - 1);
                    *(float2*)&C[((size_t)((b * NH + h) * SEQ + sq)) * HD + hd] = r2;
                }
            } else {
                *(float2*)&C[(size_t)m1 * DIM + n] = r1;
                *(float2*)&C[(size_t)m2 * DIM + n] = r2;
            }
        }
    }
}

// Fused QKV: blockIdx.z selects which projection this CTA computes.
__global__ __launch_bounds__(256, 1) void gemm_qkv(GemmArgs a0, GemmArgs a1, GemmArgs a2) {
    const GemmArgs& a = (blockIdx.z == 0) ? a0 : (blockIdx.z == 1) ? a1 : a2;
    gemm_body<1>(a.A, a.W, a.bias, a.C);
}

__global__ __launch_bounds__(256, 1) void gemm_out(const float* __restrict__ A,
                                                   const float* __restrict__ W,
                                                   const float* __restrict__ bias,
                                                   float* __restrict__ C) {
    gemm_body<0>(A, W, bias, C);
}

// ---------------------------------------------------------------------------
// Flash attention, fp32 SIMT, 4 threads per query row (each owns 16 of HD).
// Block = 256 threads = 64 query rows. K/V tile 64 rows in smem.
// ---------------------------------------------------------------------------
__global__ __launch_bounds__(256) void flash_attn(const int* __restrict__ mask,
                                                  float* __restrict__ Out) {
    const int b = blockIdx.z;
    const int h = blockIdx.y;
    const int tid = threadIdx.x;
    const int rowb = tid >> 2;          // 0..63
    const int quad = tid & 3;           // 0..3
    const int qrow = blockIdx.x * 64 + rowb;
    const int dbase = quad * 16;

    const float* Qp = g_Q + ((size_t)((b * NH + h) * SEQ) + qrow) * HD + dbase;
    const float* Kb = g_K + ((size_t)((b * NH + h) * SEQ)) * HD;
    const float* Vb = g_V + ((size_t)((b * NH + h) * SEQ)) * HD;

    float q[16];
#pragma unroll
    for (int i = 0; i < 4; i++) {
        float4 v = *(const float4*)&Qp[i * 4];
        q[i * 4 + 0] = v.x; q[i * 4 + 1] = v.y; q[i * 4 + 2] = v.z; q[i * 4 + 3] = v.w;
    }

    float o[16];
#pragma unroll
    for (int d = 0; d < 16; d++) o[d] = 0.f;
    float mx = -1e30f;
    float l = 0.f;
    const float scale = 0.125f;   // 1/sqrt(64)

    __shared__ float Ks[64 * HD];
    __shared__ float Vs[64 * HD];
    __shared__ int msk[64];

    for (int kt = 0; kt < SEQ / 64; kt++) {
        __syncthreads();
#pragma unroll
        for (int t = 0; t < 4; t++) {
            int idx = tid + t * 256;            // 0..1023 float4 chunks
            int row = idx >> 4;
            int c = (idx & 15) * 4;
            *(float4*)&Ks[row * HD + c] = *(const float4*)&Kb[((size_t)(kt * 64 + row)) * HD + c];
            *(float4*)&Vs[row * HD + c] = *(const float4*)&Vb[((size_t)(kt * 64 + row)) * HD + c];
        }
        if (tid < 64) msk[tid] = mask[b * SEQ + kt * 64 + tid];
        __syncthreads();

#pragma unroll 1
        for (int j = 0; j < 64; j++) {
            float s = 0.f;
            const float4* kr = (const float4*)&Ks[j * HD + dbase];
#pragma unroll
            for (int d4 = 0; d4 < 4; d4++) {
                float4 kv = kr[d4];
                s += q[d4 * 4 + 0] * kv.x;
                s += q[d4 * 4 + 1] * kv.y;
                s += q[d4 * 4 + 2] * kv.z;
                s += q[d4 * 4 + 3] * kv.w;
            }
            // reduce partial dot across the 4-lane quad
            s += __shfl_xor_sync(0xFFFFFFFF, s, 1);
            s += __shfl_xor_sync(0xFFFFFFFF, s, 2);
            s *= scale;
            if (msk[j]) s = -1e38f;

            float p;
            if (s > mx) {
                float corr = __expf(mx - s);
                l *= corr;
#pragma unroll
                for (int d = 0; d < 16; d++) o[d] *= corr;
                mx = s;
                p = 1.f;
            } else {
                p = __expf(s - mx);
            }
            l += p;

            const float4* vr = (const float4*)&Vs[j * HD + dbase];
#pragma unroll
            for (int d4 = 0; d4 < 4; d4++) {
                float4 vv = vr[d4];
                o[d4 * 4 + 0] += p * vv.x;
                o[d4 * 4 + 1] += p * vv.y;
                o[d4 * 4 + 2] += p * vv.z;
                o[d4 * 4 + 3] += p * vv.w;
            }
        }
    }

    const float inv = 1.f / l;
    float* Op = Out + ((size_t)(b * SEQ + qrow)) * DIM + h * HD + dbase;
#pragma unroll
    for (int i = 0; i < 4; i++) {
        float4 v;
        v.x = o[i * 4 + 0] * inv;
        v.y = o[i * 4 + 1] * inv;
        v.z = o[i * 4 + 2] * inv;
        v.w = o[i * 4 + 3] * inv;
        *(float4*)&Op[i * 4] = v;
    }
}

// ---------------------------------------------------------------------------
extern "C" void kernel_launch(void* const* d_in, const int* in_sizes, int n_in,
                              void* d_out, int out_size) {
    const float* q  = (const float*)d_in[0];
    const float* k  = (const float*)d_in[1];
    const float* v  = (const float*)d_in[2];
    const int* mask = (const int*)d_in[3];
    const float* Wq = (const float*)d_in[4];
    const float* bq = (const float*)d_in[5];
    const float* Wk = (const float*)d_in[6];
    const float* bk = (const float*)d_in[7];
    const float* Wv = (const float*)d_in[8];
    const float* bv = (const float*)d_in[9];
    const float* Wo = (const float*)d_in[10];
    const float* bo = (const float*)d_in[11];
    float* out = (float*)d_out;

    float *pQ, *pK, *pV, *pA;
    cudaGetSymbolAddress((void**)&pQ, g_Q);
    cudaGetSymbolAddress((void**)&pK, g_K);
    cudaGetSymbolAddress((void**)&pV, g_V);
    cudaGetSymbolAddress((void**)&pA, g_A);

    cudaFuncSetAttribute(gemm_qkv, cudaFuncAttributeMaxDynamicSharedMemorySize, SM_GEMM_TOTAL);
    cudaFuncSetAttribute(gemm_out, cudaFuncAttributeMaxDynamicSharedMemorySize, SM_GEMM_TOTAL);

    GemmArgs aq{q, Wq, bq, pQ};
    GemmArgs ak{k, Wk, bk, pK};
    GemmArgs av{v, Wv, bv, pV};

    dim3 gqkv(DIM / GBN, MROWS / GBM, 3);   // (4, 32, 3) = 384 CTAs
    gemm_qkv<<<gqkv, 256, SM_GEMM_TOTAL>>>(aq, ak, av);

    flash_attn<<<dim3(SEQ / 64, NH, BATCH), 256>>>(mask, pA);

    dim3 go(DIM / GBN, MROWS / GBM);        // (4, 32)
    gemm_out<<<go, 256, SM_GEMM_TOTAL>>>(pA, Wo, bo, out);
}

// round 4
// speedup vs baseline: 4.1969x; 4.1969x over previous
#include <cuda_runtime.h>
#include <cstdint>

// Problem constants
#define BATCH 2
#define SEQ   2048
#define DIM   1024
#define NH    16
#define HD    64
#define MROWS (BATCH * SEQ)   // 4096

// Scratch (allocation-free rule: __device__ globals)
__device__ float g_Q[BATCH * NH * SEQ * HD];   // [b,h,s,hd]
__device__ float g_K[BATCH * NH * SEQ * HD];
__device__ float g_V[BATCH * NH * SEQ * HD];
__device__ float g_A[BATCH * SEQ * DIM];       // attention out, [b,s,h*hd]

// ---------------------------------------------------------------------------
// Helpers
// ---------------------------------------------------------------------------
__device__ __forceinline__ uint32_t smem_u32(const void* p) {
    uint32_t a;
    asm("{ .reg .u64 t; cvta.to.shared.u64 t, %1; cvt.u32.u64 %0, t; }" : "=r"(a) : "l"(p));
    return a;
}

#define CP_ASYNC16(dst, src) \
    asm volatile("cp.async.cg.shared.global [%0], [%1], 16;" :: "r"(dst), "l"(src))
#define CP_ASYNC4(dst, src) \
    asm volatile("cp.async.ca.shared.global [%0], [%1], 4;" :: "r"(dst), "l"(src))
#define CP_ASYNC_COMMIT() asm volatile("cp.async.commit_group;" ::: "memory")
#define CP_ASYNC_WAIT(n)  asm volatile("cp.async.wait_group %0;" :: "n"(n) : "memory")

__device__ __forceinline__ uint32_t f2tf32(float x) {
    uint32_t r;
    asm("cvt.rna.tf32.f32 %0, %1;" : "=r"(r) : "f"(x));
    return r;
}

#define MMA_TF32(d, av, bv)                                                   \
    asm volatile("mma.sync.aligned.m16n8k8.row.col.f32.tf32.tf32.f32 "        \
                 "{%0,%1,%2,%3}, {%4,%5,%6,%7}, {%8,%9}, {%0,%1,%2,%3};"      \
                 : "+f"((d)[0]), "+f"((d)[1]), "+f"((d)[2]), "+f"((d)[3])     \
                 : "r"((av)[0]), "r"((av)[1]), "r"((av)[2]), "r"((av)[3]),    \
                   "r"((bv)[0]), "r"((bv)[1]))

// Fast exp2 on the FMA pipe (avoids MUFU rt=8 bottleneck). Input expected <= 0.
// Magic-number round-to-nearest + deg-5 Taylor of 2^f on [-0.5,0.5] + exponent
// bit-add. Rel err ~3e-6.
__device__ __forceinline__ float fast_exp2(float x) {
    x = fmaxf(x, -126.0f);
    float t = x + 12582912.0f;            // 2^23 + 2^22
    float i = t - 12582912.0f;
    float f = x - i;
    float p = 1.3333558e-3f;
    p = fmaf(p, f, 9.6181291e-3f);
    p = fmaf(p, f, 5.5504109e-2f);
    p = fmaf(p, f, 2.4022651e-1f);
    p = fmaf(p, f, 6.9314718e-1f);
    p = fmaf(p, f, 1.0f);
    int ib = __float_as_int(t) << 23;     // == i << 23 exactly
    return __int_as_float(__float_as_int(p) + ib);
}

// ---------------------------------------------------------------------------
// tf32 mma.sync GEMM (unchanged from R3, proven): C = A @ W^T + bias
// ---------------------------------------------------------------------------
#define GBM 128
#define GBN 256
#define GBK 32
#define NKT (DIM / GBK)                 // 32
#define SA_BYTES (GBM * GBK * 4)        // 16384
#define SB_BYTES (GBN * GBK * 4)        // 32768
#define SM_GEMM_TOTAL (2 * (SA_BYTES + SB_BYTES))   // 98304

struct GemmArgs {
    const float* A;
    const float* W;
    const float* bias;
    float* C;
};

template <int SPLIT_HEADS>
__device__ __forceinline__ void gemm_body(const float* __restrict__ A,
                                          const float* __restrict__ W,
                                          const float* __restrict__ bias,
                                          float* __restrict__ C) {
    extern __shared__ char smem[];
    float* sAf = (float*)smem;                       // [2][128][32]
    float* sBf = (float*)(smem + 2 * SA_BYTES);      // [2][256][32]
    const uint32_t sA = smem_u32(smem);
    const uint32_t sB = sA + 2 * SA_BYTES;

    const int tid = threadIdx.x;
    const int lane = tid & 31;
    const int wid = tid >> 5;
    const int wm = wid & 1;
    const int wn = wid >> 1;
    const int g = lane >> 2;
    const int tig = lane & 3;
    const int m0 = blockIdx.y * GBM;
    const int n0 = blockIdx.x * GBN;

    float acc[4][8][4];
#pragma unroll
    for (int i = 0; i < 4; i++)
#pragma unroll
        for (int j = 0; j < 8; j++)
#pragma unroll
            for (int c = 0; c < 4; c++) acc[i][j][c] = 0.f;

    auto stage = [&](int kt, int buf) {
        const int k0 = kt * GBK;
#pragma unroll
        for (int t = 0; t < 4; t++) {
            int idx = tid + t * 256;
            int row = idx >> 3;
            int c = idx & 7;
            uint32_t dst = sA + buf * SA_BYTES + row * 128 + ((c ^ (row & 7)) << 4);
            CP_ASYNC16(dst, &A[(size_t)(m0 + row) * DIM + k0 + c * 4]);
        }
#pragma unroll
        for (int t = 0; t < 8; t++) {
            int idx = tid + t * 256;
            int row = idx >> 3;
            int c = idx & 7;
            uint32_t dst = sB + buf * SB_BYTES + row * 128 + ((c ^ (row & 7)) << 4);
            CP_ASYNC16(dst, &W[(size_t)(n0 + row) * DIM + k0 + c * 4]);
        }
    };

    stage(0, 0);
    CP_ASYNC_COMMIT();

    for (int kt = 0; kt < NKT; kt++) {
        if (kt + 1 < NKT) {
            stage(kt + 1, (kt + 1) & 1);
            CP_ASYNC_COMMIT();
            CP_ASYNC_WAIT(1);
        } else {
            CP_ASYNC_WAIT(0);
        }
        __syncthreads();

        const float* Ab = sAf + (kt & 1) * (SA_BYTES / 4);
        const float* Bb = sBf + (kt & 1) * (SB_BYTES / 4);
#pragma unroll
        for (int s = 0; s < 4; s++) {
            const int k1 = s * 8 + tig;
            const int k2 = k1 + 4;
            uint32_t a[4][4];
#pragma unroll
            for (int i = 0; i < 4; i++) {
                int r1 = wm * 64 + i * 16 + g;
                int r2 = r1 + 8;
                a[i][0] = f2tf32(Ab[r1 * 32 + (k1 ^ ((r1 & 7) << 2))]);
                a[i][1] = f2tf32(Ab[r2 * 32 + (k1 ^ ((r2 & 7) << 2))]);
                a[i][2] = f2tf32(Ab[r1 * 32 + (k2 ^ ((r1 & 7) << 2))]);
                a[i][3] = f2tf32(Ab[r2 * 32 + (k2 ^ ((r2 & 7) << 2))]);
            }
            uint32_t bf[8][2];
#pragma unroll
            for (int j = 0; j < 8; j++) {
                int rn = wn * 64 + j * 8 + g;
                bf[j][0] = f2tf32(Bb[rn * 32 + (k1 ^ ((rn & 7) << 2))]);
                bf[j][1] = f2tf32(Bb[rn * 32 + (k2 ^ ((rn & 7) << 2))]);
            }
#pragma unroll
            for (int i = 0; i < 4; i++)
#pragma unroll
                for (int j = 0; j < 8; j++) MMA_TF32(acc[i][j], a[i], bf[j]);
        }
        __syncthreads();
    }

#pragma unroll
    for (int i = 0; i < 4; i++) {
        const int m1 = m0 + wm * 64 + i * 16 + g;
        const int m2 = m1 + 8;
#pragma unroll
        for (int j = 0; j < 8; j++) {
            const int n = n0 + wn * 64 + j * 8 + tig * 2;
            const float2 bb = *(const float2*)&bias[n];
            float2 r1, r2;
            r1.x = acc[i][j][0] + bb.x;
            r1.y = acc[i][j][1] + bb.y;
            r2.x = acc[i][j][2] + bb.x;
            r2.y = acc[i][j][3] + bb.y;
            if (SPLIT_HEADS) {
                int h = n >> 6;
                int hd = n & (HD - 1);
                {
                    int b = m1 >> 11, sq = m1 & (SEQ - 1);
                    *(float2*)&C[((size_t)((b * NH + h) * SEQ + sq)) * HD + hd] = r1;
                }
                {
                    int b = m2 >> 11, sq = m2 & (SEQ - 1);
                    *(float2*)&C[((size_t)((b * NH + h) * SEQ + sq)) * HD + hd] = r2;
                }
            } else {
                *(float2*)&C[(size_t)m1 * DIM + n] = r1;
                *(float2*)&C[(size_t)m2 * DIM + n] = r2;
            }
        }
    }
}

__global__ __launch_bounds__(256, 1) void gemm_qkv(GemmArgs a0, GemmArgs a1, GemmArgs a2) {
    const GemmArgs& a = (blockIdx.z == 0) ? a0 : (blockIdx.z == 1) ? a1 : a2;
    gemm_body<1>(a.A, a.W, a.bias, a.C);
}

__global__ __launch_bounds__(256, 1) void gemm_out(const float* __restrict__ A,
                                                   const float* __restrict__ W,
                                                   const float* __restrict__ bias,
                                                   float* __restrict__ C) {
    gemm_body<0>(A, W, bias, C);
}

// ---------------------------------------------------------------------------
// Tensor-core flash attention (tf32 mma.sync).
// CTA: 256 thr (8 warps) = 128 query rows of one (b,h); warp owns 16 rows.
// KV tiled 64 at a time, cp.async double-buffered. P routed via padded smem.
// ---------------------------------------------------------------------------
#define FKT 64
#define KVS 72          // smem row stride (floats): conflict-free frag loads
#define FNT (SEQ / FKT) // 32

// smem float offsets
#define F_KSM 0
#define F_VSM (2 * FKT * KVS)                 // 9216
#define F_PSM (F_VSM + 2 * FKT * KVS)         // 18432
#define F_MSK (F_PSM + 8 * 16 * KVS)          // 27648 (int region)
#define F_TOTAL_FLOATS (F_MSK + 2 * FKT)      // 27776
#define FLASH_SMEM_BYTES (F_TOTAL_FLOATS * 4) // 111104

#define CS 0.18033688f  // 0.125 * log2(e)

__global__ __launch_bounds__(256, 1) void flash_attn_tc(const int* __restrict__ mask,
                                                        float* __restrict__ Out) {
    extern __shared__ char smem[];
    float* smf = (float*)smem;
    int* smi = (int*)smem;
    const uint32_t sbase = smem_u32(smem);

    const int b = blockIdx.z;
    const int h = blockIdx.y;
    const int tid = threadIdx.x;
    const int w = tid >> 5;
    const int lane = tid & 31;
    const int g = lane >> 2;       // 0..7
    const int tig = lane & 3;      // 0..3
    const int qr0 = blockIdx.x * 128 + w * 16;

    const float* Qp = g_Q + ((size_t)((b * NH + h) * SEQ) + qr0) * HD;
    const float* Kb = g_K + ((size_t)((b * NH + h) * SEQ)) * HD;
    const float* Vb = g_V + ((size_t)((b * NH + h) * SEQ)) * HD;
    const int* mb = mask + b * SEQ;

    // Persistent Q A-fragments (tf32)
    uint32_t aQ[8][4];
#pragma unroll
    for (int s = 0; s < 8; s++) {
        aQ[s][0] = f2tf32(Qp[g * HD + 8 * s + tig]);
        aQ[s][1] = f2tf32(Qp[(g + 8) * HD + 8 * s + tig]);
        aQ[s][2] = f2tf32(Qp[g * HD + 8 * s + tig + 4]);
        aQ[s][3] = f2tf32(Qp[(g + 8) * HD + 8 * s + tig + 4]);
    }

    float oacc[8][4];
#pragma unroll
    for (int j = 0; j < 8; j++)
#pragma unroll
        for (int c = 0; c < 4; c++) oacc[j][c] = 0.f;
    float m0 = -1e30f, m1 = -1e30f;   // log2-domain running max (rows g, g+8)
    float l0 = 0.f, l1 = 0.f;

    auto stage = [&](int kt, int buf) {
        const float* Kg = Kb + (size_t)kt * FKT * HD;
        const float* Vg = Vb + (size_t)kt * FKT * HD;
        const uint32_t dK = sbase + (F_KSM + buf * FKT * KVS) * 4;
        const uint32_t dV = sbase + (F_VSM + buf * FKT * KVS) * 4;
#pragma unroll
        for (int t = 0; t < 4; t++) {
            int idx = tid + t * 256;       // 0..1023
            int row = idx >> 4;
            int c = idx & 15;
            CP_ASYNC16(dK + row * (KVS * 4) + c * 16, &Kg[row * HD + c * 4]);
            CP_ASYNC16(dV + row * (KVS * 4) + c * 16, &Vg[row * HD + c * 4]);
        }
        if (tid < FKT) {
            CP_ASYNC4(sbase + (F_MSK + buf * FKT + tid) * 4, &mb[kt * FKT + tid]);
        }
    };

    stage(0, 0);
    CP_ASYNC_COMMIT();

    uint32_t* Pw = (uint32_t*)(smf + F_PSM + w * 16 * KVS);

    for (int kt = 0; kt < FNT; kt++) {
        if (kt + 1 < FNT) {
            stage(kt + 1, (kt + 1) & 1);
            CP_ASYNC_COMMIT();
            CP_ASYNC_WAIT(1);
        } else {
            CP_ASYNC_WAIT(0);
        }
        __syncthreads();

        const int buf = kt & 1;
        const float* Kbuf = smf + F_KSM + buf * FKT * KVS;
        const float* Vbuf = smf + F_VSM + buf * FKT * KVS;
        const int* mk = smi + F_MSK + buf * FKT;

        // ---- S = Q @ K^T (16 x 64 per warp) ----
        float sc[8][4];
#pragma unroll
        for (int j = 0; j < 8; j++)
#pragma unroll
            for (int c = 0; c < 4; c++) sc[j][c] = 0.f;
#pragma unroll
        for (int s = 0; s < 8; s++) {
#pragma unroll
            for (int jn = 0; jn < 8; jn++) {
                uint32_t bf[2];
                bf[0] = f2tf32(Kbuf[(8 * jn + g) * KVS + 8 * s + tig]);
                bf[1] = f2tf32(Kbuf[(8 * jn + g) * KVS + 8 * s + tig + 4]);
                MMA_TF32(sc[jn], aQ[s], bf);
            }
        }

        // ---- online softmax (log2 domain) ----
#pragma unroll
        for (int jn = 0; jn < 8; jn++) {
            int2 mv = *(const int2*)&mk[8 * jn + 2 * tig];
            float ax = mv.x ? -1e30f : 0.f;
            float ay = mv.y ? -1e30f : 0.f;
            sc[jn][0] = fmaf(sc[jn][0], CS, ax);
            sc[jn][1] = fmaf(sc[jn][1], CS, ay);
            sc[jn][2] = fmaf(sc[jn][2], CS, ax);
            sc[jn][3] = fmaf(sc[jn][3], CS, ay);
        }
        float mx0 = -1e30f, mx1 = -1e30f;
#pragma unroll
        for (int jn = 0; jn < 8; jn++) {
            mx0 = fmaxf(mx0, fmaxf(sc[jn][0], sc[jn][1]));
            mx1 = fmaxf(mx1, fmaxf(sc[jn][2], sc[jn][3]));
        }
        mx0 = fmaxf(mx0, __shfl_xor_sync(0xFFFFFFFF, mx0, 1));
        mx0 = fmaxf(mx0, __shfl_xor_sync(0xFFFFFFFF, mx0, 2));
        mx1 = fmaxf(mx1, __shfl_xor_sync(0xFFFFFFFF, mx1, 1));
        mx1 = fmaxf(mx1, __shfl_xor_sync(0xFFFFFFFF, mx1, 2));

        const float nm0 = fmaxf(m0, mx0);
        const float nm1 = fmaxf(m1, mx1);
        const float cor0 = fast_exp2(m0 - nm0);
        const float cor1 = fast_exp2(m1 - nm1);
        m0 = nm0; m1 = nm1;

        float s0 = 0.f, s1 = 0.f;
#pragma unroll
        for (int jn = 0; jn < 8; jn++) {
            sc[jn][0] = fast_exp2(sc[jn][0] - nm0);
            sc[jn][1] = fast_exp2(sc[jn][1] - nm0);
            sc[jn][2] = fast_exp2(sc[jn][2] - nm1);
            sc[jn][3] = fast_exp2(sc[jn][3] - nm1);
            s0 += sc[jn][0] + sc[jn][1];
            s1 += sc[jn][2] + sc[jn][3];
        }
        s0 += __shfl_xor_sync(0xFFFFFFFF, s0, 1);
        s0 += __shfl_xor_sync(0xFFFFFFFF, s0, 2);
        s1 += __shfl_xor_sync(0xFFFFFFFF, s1, 1);
        s1 += __shfl_xor_sync(0xFFFFFFFF, s1, 2);
        l0 = l0 * cor0 + s0;
        l1 = l1 * cor1 + s1;

#pragma unroll
        for (int j = 0; j < 8; j++) {
            oacc[j][0] *= cor0;
            oacc[j][1] *= cor0;
            oacc[j][2] *= cor1;
            oacc[j][3] *= cor1;
        }

        // ---- P -> smem (tf32 bits), then O += P @ V ----
#pragma unroll
        for (int jn = 0; jn < 8; jn++) {
            Pw[g * KVS + 8 * jn + 2 * tig]           = f2tf32(sc[jn][0]);
            Pw[g * KVS + 8 * jn + 2 * tig + 1]       = f2tf32(sc[jn][1]);
            Pw[(g + 8) * KVS + 8 * jn + 2 * tig]     = f2tf32(sc[jn][2]);
            Pw[(g + 8) * KVS + 8 * jn + 2 * tig + 1] = f2tf32(sc[jn][3]);
        }
        __syncwarp();

#pragma unroll
        for (int s2 = 0; s2 < 8; s2++) {
            uint32_t pa[4];
            pa[0] = Pw[g * KVS + 8 * s2 + tig];
            pa[1] = Pw[(g + 8) * KVS + 8 * s2 + tig];
            pa[2] = Pw[g * KVS + 8 * s2 + tig + 4];
            pa[3] = Pw[(g + 8) * KVS + 8 * s2 + tig + 4];
#pragma unroll
            for (int jn2 = 0; jn2 < 8; jn2++) {
                uint32_t bf[2];
                bf[0] = f2tf32(Vbuf[(8 * s2 + tig) * KVS + 8 * jn2 + g]);
                bf[1] = f2tf32(Vbuf[(8 * s2 + tig + 4) * KVS + 8 * jn2 + g]);
                MMA_TF32(oacc[jn2], pa, bf);
            }
        }
        __syncthreads();   // all warps done with this buf before restaging
    }

    // ---- epilogue: normalize + store to [b, s, h*64+hd] ----
    const float il0 = 1.f / l0;
    const float il1 = 1.f / l1;
    float* O0 = Out + ((size_t)(b * SEQ + qr0 + g)) * DIM + h * HD;
    float* O1 = Out + ((size_t)(b * SEQ + qr0 + g + 8)) * DIM + h * HD;
#pragma unroll
    for (int jn2 = 0; jn2 < 8; jn2++) {
        float2 r0, r1;
        r0.x = oacc[jn2][0] * il0;
        r0.y = oacc[jn2][1] * il0;
        r1.x = oacc[jn2][2] * il1;
        r1.y = oacc[jn2][3] * il1;
        *(float2*)&O0[8 * jn2 + 2 * tig] = r0;
        *(float2*)&O1[8 * jn2 + 2 * tig] = r1;
    }
}

// ---------------------------------------------------------------------------
extern "C" void kernel_launch(void* const* d_in, const int* in_sizes, int n_in,
                              void* d_out, int out_size) {
    const float* q  = (const float*)d_in[0];
    const float* k  = (const float*)d_in[1];
    const float* v  = (const float*)d_in[2];
    const int* mask = (const int*)d_in[3];
    const float* Wq = (const float*)d_in[4];
    const float* bq = (const float*)d_in[5];
    const float* Wk = (const float*)d_in[6];
    const float* bk = (const float*)d_in[7];
    const float* Wv = (const float*)d_in[8];
    const float* bv = (const float*)d_in[9];
    const float* Wo = (const float*)d_in[10];
    const float* bo = (const float*)d_in[11];
    float* out = (float*)d_out;

    float *pQ, *pK, *pV, *pA;
    cudaGetSymbolAddress((void**)&pQ, g_Q);
    cudaGetSymbolAddress((void**)&pK, g_K);
    cudaGetSymbolAddress((void**)&pV, g_V);
    cudaGetSymbolAddress((void**)&pA, g_A);

    cudaFuncSetAttribute(gemm_qkv, cudaFuncAttributeMaxDynamicSharedMemorySize, SM_GEMM_TOTAL);
    cudaFuncSetAttribute(gemm_out, cudaFuncAttributeMaxDynamicSharedMemorySize, SM_GEMM_TOTAL);
    cudaFuncSetAttribute(flash_attn_tc, cudaFuncAttributeMaxDynamicSharedMemorySize, FLASH_SMEM_BYTES);

    GemmArgs aq{q, Wq, bq, pQ};
    GemmArgs ak{k, Wk, bk, pK};
    GemmArgs av{v, Wv, bv, pV};

    dim3 gqkv(DIM / GBN, MROWS / GBM, 3);   // 384 CTAs
    gemm_qkv<<<gqkv, 256, SM_GEMM_TOTAL>>>(aq, ak, av);

    flash_attn_tc<<<dim3(SEQ / 128, NH, BATCH), 256, FLASH_SMEM_BYTES>>>(mask, pA);

    dim3 go(DIM / GBN, MROWS / GBM);        // 128 CTAs
    gemm_out<<<go, 256, SM_GEMM_TOTAL>>>(pA, Wo, bo, out);
}

// round 5
// speedup vs baseline: 4.6190x; 1.1006x over previous
#include <cuda_runtime.h>
#include <cstdint>

// Problem constants
#define BATCH 2
#define SEQ   2048
#define DIM   1024
#define NH    16
#define HD    64
#define MROWS (BATCH * SEQ)   // 4096

// Scratch (allocation-free rule: __device__ globals)
__device__ float g_Q[BATCH * NH * SEQ * HD];   // [b,h,s,hd] (tf32-rounded)
__device__ float g_K[BATCH * NH * SEQ * HD];   // (tf32-rounded)
__device__ float g_V[BATCH * NH * SEQ * HD];   // (tf32-rounded)
__device__ float g_A[BATCH * SEQ * DIM];       // attn out [b,s,h*hd] (tf32-rounded)
__device__ float g_Wc[4 * DIM * DIM];          // tf32-rounded Wq,Wk,Wv,Wo
__device__ float g_Xc[3 * MROWS * DIM];        // tf32-rounded q,k,v

// ---------------------------------------------------------------------------
// Helpers
// ---------------------------------------------------------------------------
__device__ __forceinline__ uint32_t smem_u32(const void* p) {
    uint32_t a;
    asm("{ .reg .u64 t; cvta.to.shared.u64 t, %1; cvt.u32.u64 %0, t; }" : "=r"(a) : "l"(p));
    return a;
}

#define CP_ASYNC16(dst, src) \
    asm volatile("cp.async.cg.shared.global [%0], [%1], 16;" :: "r"(dst), "l"(src))
#define CP_ASYNC4(dst, src) \
    asm volatile("cp.async.ca.shared.global [%0], [%1], 4;" :: "r"(dst), "l"(src))
#define CP_ASYNC_COMMIT() asm volatile("cp.async.commit_group;" ::: "memory")
#define CP_ASYNC_WAIT(n)  asm volatile("cp.async.wait_group %0;" :: "n"(n) : "memory")

__device__ __forceinline__ uint32_t f2tf32(float x) {
    uint32_t r;
    asm("cvt.rna.tf32.f32 %0, %1;" : "=r"(r) : "f"(x));
    return r;
}

#define MMA_TF32(d, av, bv)                                                   \
    asm volatile("mma.sync.aligned.m16n8k8.row.col.f32.tf32.tf32.f32 "        \
                 "{%0,%1,%2,%3}, {%4,%5,%6,%7}, {%8,%9}, {%0,%1,%2,%3};"      \
                 : "+f"((d)[0]), "+f"((d)[1]), "+f"((d)[2]), "+f"((d)[3])     \
                 : "r"((av)[0]), "r"((av)[1]), "r"((av)[2]), "r"((av)[3]),    \
                   "r"((bv)[0]), "r"((bv)[1]))

// Fast exp2 on the FMA pipe. Rel err ~3e-6.
__device__ __forceinline__ float fast_exp2(float x) {
    x = fmaxf(x, -126.0f);
    float t = x + 12582912.0f;            // 2^23 + 2^22
    float i = t - 12582912.0f;
    float f = x - i;
    float p = 1.3333558e-3f;
    p = fmaf(p, f, 9.6181291e-3f);
    p = fmaf(p, f, 5.5504109e-2f);
    p = fmaf(p, f, 2.4022651e-1f);
    p = fmaf(p, f, 6.9314718e-1f);
    p = fmaf(p, f, 1.0f);
    int ib = __float_as_int(t) << 23;     // == i << 23 exactly
    return __int_as_float(__float_as_int(p) + ib);
}

// ---------------------------------------------------------------------------
// One-time tf32 rounding pre-pass (bitwise round, stored as float)
// ---------------------------------------------------------------------------
__global__ __launch_bounds__(256) void conv_tf32(const float* __restrict__ src,
                                                 float* __restrict__ dst, int n4) {
    int i = blockIdx.x * 256 + threadIdx.x;
    if (i < n4) {
        float4 v = ((const float4*)src)[i];
        float4 r;
        r.x = __uint_as_float(f2tf32(v.x));
        r.y = __uint_as_float(f2tf32(v.y));
        r.z = __uint_as_float(f2tf32(v.z));
        r.w = __uint_as_float(f2tf32(v.w));
        ((float4*)dst)[i] = r;
    }
}

// ---------------------------------------------------------------------------
// tf32 mma.sync GEMM: C = A @ W^T + bias. A and W hold pre-rounded tf32 bits.
// CTA tile 128x256, BK=32, 8 warps (2x4), 64x64 each. XOR-swizzled smem.
// ---------------------------------------------------------------------------
#define GBM 128
#define GBN 256
#define GBK 32
#define NKT (DIM / GBK)                 // 32
#define SA_BYTES (GBM * GBK * 4)        // 16384
#define SB_BYTES (GBN * GBK * 4)        // 32768
#define SM_GEMM_TOTAL (2 * (SA_BYTES + SB_BYTES))   // 98304

struct GemmArgs {
    const float* A;
    const float* W;
    const float* bias;
    float* C;
};

template <int SPLIT_HEADS>
__device__ __forceinline__ void gemm_body(const float* __restrict__ A,
                                          const float* __restrict__ W,
                                          const float* __restrict__ bias,
                                          float* __restrict__ C) {
    extern __shared__ char smem[];
    const float* sAf = (const float*)smem;               // [2][128][32]
    const float* sBf = (const float*)(smem + 2 * SA_BYTES);
    const uint32_t sA = smem_u32(smem);
    const uint32_t sB = sA + 2 * SA_BYTES;

    const int tid = threadIdx.x;
    const int lane = tid & 31;
    const int wid = tid >> 5;
    const int wm = wid & 1;
    const int wn = wid >> 1;
    const int g = lane >> 2;
    const int tig = lane & 3;
    const int m0 = blockIdx.y * GBM;
    const int n0 = blockIdx.x * GBN;

    float acc[4][8][4];
#pragma unroll
    for (int i = 0; i < 4; i++)
#pragma unroll
        for (int j = 0; j < 8; j++)
#pragma unroll
            for (int c = 0; c < 4; c++) acc[i][j][c] = 0.f;

    auto stage = [&](int kt, int buf) {
        const int k0 = kt * GBK;
#pragma unroll
        for (int t = 0; t < 4; t++) {
            int idx = tid + t * 256;
            int row = idx >> 3;
            int c = idx & 7;
            uint32_t dst = sA + buf * SA_BYTES + row * 128 + ((c ^ (row & 7)) << 4);
            CP_ASYNC16(dst, &A[(size_t)(m0 + row) * DIM + k0 + c * 4]);
        }
#pragma unroll
        for (int t = 0; t < 8; t++) {
            int idx = tid + t * 256;
            int row = idx >> 3;
            int c = idx & 7;
            uint32_t dst = sB + buf * SB_BYTES + row * 128 + ((c ^ (row & 7)) << 4);
            CP_ASYNC16(dst, &W[(size_t)(n0 + row) * DIM + k0 + c * 4]);
        }
    };

    stage(0, 0);
    CP_ASYNC_COMMIT();

    for (int kt = 0; kt < NKT; kt++) {
        if (kt + 1 < NKT) {
            stage(kt + 1, (kt + 1) & 1);
            CP_ASYNC_COMMIT();
            CP_ASYNC_WAIT(1);
        } else {
            CP_ASYNC_WAIT(0);
        }
        __syncthreads();

        const float* Ab = sAf + (kt & 1) * (SA_BYTES / 4);
        const float* Bb = sBf + (kt & 1) * (SB_BYTES / 4);
#pragma unroll
        for (int s = 0; s < 4; s++) {
            const int k1 = s * 8 + tig;
            const int k2 = k1 + 4;
            uint32_t a[4][4];
#pragma unroll
            for (int i = 0; i < 4; i++) {
                int r1 = wm * 64 + i * 16 + g;
                int r2 = r1 + 8;
                a[i][0] = __float_as_uint(Ab[r1 * 32 + (k1 ^ ((r1 & 7) << 2))]);
                a[i][1] = __float_as_uint(Ab[r2 * 32 + (k1 ^ ((r2 & 7) << 2))]);
                a[i][2] = __float_as_uint(Ab[r1 * 32 + (k2 ^ ((r1 & 7) << 2))]);
                a[i][3] = __float_as_uint(Ab[r2 * 32 + (k2 ^ ((r2 & 7) << 2))]);
            }
            uint32_t bf[8][2];
#pragma unroll
            for (int j = 0; j < 8; j++) {
                int rn = wn * 64 + j * 8 + g;
                bf[j][0] = __float_as_uint(Bb[rn * 32 + (k1 ^ ((rn & 7) << 2))]);
                bf[j][1] = __float_as_uint(Bb[rn * 32 + (k2 ^ ((rn & 7) << 2))]);
            }
#pragma unroll
            for (int i = 0; i < 4; i++)
#pragma unroll
                for (int j = 0; j < 8; j++) MMA_TF32(acc[i][j], a[i], bf[j]);
        }
        __syncthreads();
    }

#pragma unroll
    for (int i = 0; i < 4; i++) {
        const int m1 = m0 + wm * 64 + i * 16 + g;
        const int m2 = m1 + 8;
#pragma unroll
        for (int j = 0; j < 8; j++) {
            const int n = n0 + wn * 64 + j * 8 + tig * 2;
            const float2 bb = *(const float2*)&bias[n];
            float2 r1, r2;
            if (SPLIT_HEADS) {
                // store tf32-rounded so flash skips per-use conversion
                r1.x = __uint_as_float(f2tf32(acc[i][j][0] + bb.x));
                r1.y = __uint_as_float(f2tf32(acc[i][j][1] + bb.y));
                r2.x = __uint_as_float(f2tf32(acc[i][j][2] + bb.x));
                r2.y = __uint_as_float(f2tf32(acc[i][j][3] + bb.y));
                int h = n >> 6;
                int hd = n & (HD - 1);
                {
                    int b = m1 >> 11, sq = m1 & (SEQ - 1);
                    *(float2*)&C[((size_t)((b * NH + h) * SEQ + sq)) * HD + hd] = r1;
                }
                {
                    int b = m2 >> 11, sq = m2 & (SEQ - 1);
                    *(float2*)&C[((size_t)((b * NH + h) * SEQ + sq)) * HD + hd] = r2;
                }
            } else {
                r1.x = acc[i][j][0] + bb.x;
                r1.y = acc[i][j][1] + bb.y;
                r2.x = acc[i][j][2] + bb.x;
                r2.y = acc[i][j][3] + bb.y;
                *(float2*)&C[(size_t)m1 * DIM + n] = r1;
                *(float2*)&C[(size_t)m2 * DIM + n] = r2;
            }
        }
    }
}

__global__ __launch_bounds__(256, 1) void gemm_qkv(GemmArgs a0, GemmArgs a1, GemmArgs a2) {
    const GemmArgs& a = (blockIdx.z == 0) ? a0 : (blockIdx.z == 1) ? a1 : a2;
    gemm_body<1>(a.A, a.W, a.bias, a.C);
}

__global__ __launch_bounds__(256, 1) void gemm_out(const float* __restrict__ A,
                                                   const float* __restrict__ W,
                                                   const float* __restrict__ bias,
                                                   float* __restrict__ C) {
    gemm_body<0>(A, W, bias, C);
}

// ---------------------------------------------------------------------------
// Tensor-core flash attention (tf32 mma.sync), no in-loop cvt (inputs
// pre-rounded). 128 thr (4 warps) = 64 q-rows; smem 92.7KB -> 2 CTAs/SM.
// ---------------------------------------------------------------------------
#define FKT 64
#define KVS 72          // smem row stride (floats)
#define FNT (SEQ / FKT) // 32

#define F_KSM 0
#define F_VSM (2 * FKT * KVS)                 // 9216
#define F_PSM (F_VSM + 2 * FKT * KVS)         // 18432
#define F_MSK (F_PSM + 4 * 16 * KVS)          // 23040 (int region)
#define F_TOTAL_FLOATS (F_MSK + 2 * FKT)      // 23168
#define FLASH_SMEM_BYTES (F_TOTAL_FLOATS * 4) // 92672

#define CS 0.18033688f  // 0.125 * log2(e)

__global__ __launch_bounds__(128) void flash_attn_tc(const int* __restrict__ mask,
                                                     float* __restrict__ Out) {
    extern __shared__ char smem[];
    float* smf = (float*)smem;
    int* smi = (int*)smem;
    const uint32_t sbase = smem_u32(smem);

    const int b = blockIdx.z;
    const int h = blockIdx.y;
    const int tid = threadIdx.x;
    const int w = tid >> 5;
    const int lane = tid & 31;
    const int g = lane >> 2;       // 0..7
    const int tig = lane & 3;      // 0..3
    const int qr0 = blockIdx.x * 64 + w * 16;

    const float* Qp = g_Q + ((size_t)((b * NH + h) * SEQ) + qr0) * HD;
    const float* Kb = g_K + ((size_t)((b * NH + h) * SEQ)) * HD;
    const float* Vb = g_V + ((size_t)((b * NH + h) * SEQ)) * HD;
    const int* mb = mask + b * SEQ;

    // Persistent Q A-fragments (already tf32-rounded bits)
    uint32_t aQ[8][4];
#pragma unroll
    for (int s = 0; s < 8; s++) {
        aQ[s][0] = __float_as_uint(Qp[g * HD + 8 * s + tig]);
        aQ[s][1] = __float_as_uint(Qp[(g + 8) * HD + 8 * s + tig]);
        aQ[s][2] = __float_as_uint(Qp[g * HD + 8 * s + tig + 4]);
        aQ[s][3] = __float_as_uint(Qp[(g + 8) * HD + 8 * s + tig + 4]);
    }

    float oacc[8][4];
#pragma unroll
    for (int j = 0; j < 8; j++)
#pragma unroll
        for (int c = 0; c < 4; c++) oacc[j][c] = 0.f;
    float m0 = -1e30f, m1 = -1e30f;
    float l0 = 0.f, l1 = 0.f;

    auto stage = [&](int kt, int buf) {
        const float* Kg = Kb + (size_t)kt * FKT * HD;
        const float* Vg = Vb + (size_t)kt * FKT * HD;
        const uint32_t dK = sbase + (F_KSM + buf * FKT * KVS) * 4;
        const uint32_t dV = sbase + (F_VSM + buf * FKT * KVS) * 4;
#pragma unroll
        for (int t = 0; t < 8; t++) {
            int idx = tid + t * 128;       // 0..1023
            int row = idx >> 4;
            int c = idx & 15;
            CP_ASYNC16(dK + row * (KVS * 4) + c * 16, &Kg[row * HD + c * 4]);
            CP_ASYNC16(dV + row * (KVS * 4) + c * 16, &Vg[row * HD + c * 4]);
        }
        if (tid < FKT) {
            CP_ASYNC4(sbase + (F_MSK + buf * FKT + tid) * 4, &mb[kt * FKT + tid]);
        }
    };

    stage(0, 0);
    CP_ASYNC_COMMIT();

    uint32_t* Pw = (uint32_t*)(smf + F_PSM + w * 16 * KVS);

    for (int kt = 0; kt < FNT; kt++) {
        if (kt + 1 < FNT) {
            stage(kt + 1, (kt + 1) & 1);
            CP_ASYNC_COMMIT();
            CP_ASYNC_WAIT(1);
        } else {
            CP_ASYNC_WAIT(0);
        }
        __syncthreads();

        const int buf = kt & 1;
        const float* Kbuf = smf + F_KSM + buf * FKT * KVS;
        const float* Vbuf = smf + F_VSM + buf * FKT * KVS;
        const int* mk = smi + F_MSK + buf * FKT;

        // ---- S = Q @ K^T (16 x 64 per warp) ----
        float sc[8][4];
#pragma unroll
        for (int j = 0; j < 8; j++)
#pragma unroll
            for (int c = 0; c < 4; c++) sc[j][c] = 0.f;
#pragma unroll
        for (int s = 0; s < 8; s++) {
#pragma unroll
            for (int jn = 0; jn < 8; jn++) {
                uint32_t bf[2];
                bf[0] = __float_as_uint(Kbuf[(8 * jn + g) * KVS + 8 * s + tig]);
                bf[1] = __float_as_uint(Kbuf[(8 * jn + g) * KVS + 8 * s + tig + 4]);
                MMA_TF32(sc[jn], aQ[s], bf);
            }
        }

        // ---- online softmax (log2 domain) ----
#pragma unroll
        for (int jn = 0; jn < 8; jn++) {
            int2 mv = *(const int2*)&mk[8 * jn + 2 * tig];
            float ax = mv.x ? -1e30f : 0.f;
            float ay = mv.y ? -1e30f : 0.f;
            sc[jn][0] = fmaf(sc[jn][0], CS, ax);
            sc[jn][1] = fmaf(sc[jn][1], CS, ay);
            sc[jn][2] = fmaf(sc[jn][2], CS, ax);
            sc[jn][3] = fmaf(sc[jn][3], CS, ay);
        }
        float mx0 = -1e30f, mx1 = -1e30f;
#pragma unroll
        for (int jn = 0; jn < 8; jn++) {
            mx0 = fmaxf(mx0, fmaxf(sc[jn][0], sc[jn][1]));
            mx1 = fmaxf(mx1, fmaxf(sc[jn][2], sc[jn][3]));
        }
        mx0 = fmaxf(mx0, __shfl_xor_sync(0xFFFFFFFF, mx0, 1));
        mx0 = fmaxf(mx0, __shfl_xor_sync(0xFFFFFFFF, mx0, 2));
        mx1 = fmaxf(mx1, __shfl_xor_sync(0xFFFFFFFF, mx1, 1));
        mx1 = fmaxf(mx1, __shfl_xor_sync(0xFFFFFFFF, mx1, 2));

        const float nm0 = fmaxf(m0, mx0);
        const float nm1 = fmaxf(m1, mx1);
        const float cor0 = fast_exp2(m0 - nm0);
        const float cor1 = fast_exp2(m1 - nm1);
        m0 = nm0; m1 = nm1;

        float s0 = 0.f, s1 = 0.f;
#pragma unroll
        for (int jn = 0; jn < 8; jn++) {
            sc[jn][0] = fast_exp2(sc[jn][0] - nm0);
            sc[jn][1] = fast_exp2(sc[jn][1] - nm0);
            sc[jn][2] = fast_exp2(sc[jn][2] - nm1);
            sc[jn][3] = fast_exp2(sc[jn][3] - nm1);
            s0 += sc[jn][0] + sc[jn][1];
            s1 += sc[jn][2] + sc[jn][3];
        }
        s0 += __shfl_xor_sync(0xFFFFFFFF, s0, 1);
        s0 += __shfl_xor_sync(0xFFFFFFFF, s0, 2);
        s1 += __shfl_xor_sync(0xFFFFFFFF, s1, 1);
        s1 += __shfl_xor_sync(0xFFFFFFFF, s1, 2);
        l0 = l0 * cor0 + s0;
        l1 = l1 * cor1 + s1;

#pragma unroll
        for (int j = 0; j < 8; j++) {
            oacc[j][0] *= cor0;
            oacc[j][1] *= cor0;
            oacc[j][2] *= cor1;
            oacc[j][3] *= cor1;
        }

        // ---- P -> smem (tf32 bits), then O += P @ V ----
#pragma unroll
        for (int jn = 0; jn < 8; jn++) {
            Pw[g * KVS + 8 * jn + 2 * tig]           = f2tf32(sc[jn][0]);
            Pw[g * KVS + 8 * jn + 2 * tig + 1]       = f2tf32(sc[jn][1]);
            Pw[(g + 8) * KVS + 8 * jn + 2 * tig]     = f2tf32(sc[jn][2]);
            Pw[(g + 8) * KVS + 8 * jn + 2 * tig + 1] = f2tf32(sc[jn][3]);
        }
        __syncwarp();

#pragma unroll
        for (int s2 = 0; s2 < 8; s2++) {
            uint32_t pa[4];
            pa[0] = Pw[g * KVS + 8 * s2 + tig];
            pa[1] = Pw[(g + 8) * KVS + 8 * s2 + tig];
            pa[2] = Pw[g * KVS + 8 * s2 + tig + 4];
            pa[3] = Pw[(g + 8) * KVS + 8 * s2 + tig + 4];
#pragma unroll
            for (int jn2 = 0; jn2 < 8; jn2++) {
                uint32_t bf[2];
                bf[0] = __float_as_uint(Vbuf[(8 * s2 + tig) * KVS + 8 * jn2 + g]);
                bf[1] = __float_as_uint(Vbuf[(8 * s2 + tig + 4) * KVS + 8 * jn2 + g]);
                MMA_TF32(oacc[jn2], pa, bf);
            }
        }
        __syncthreads();   // all warps done with buf before restage
    }

    // ---- epilogue: normalize + store tf32-rounded to g_A ----
    const float il0 = 1.f / l0;
    const float il1 = 1.f / l1;
    float* O0 = Out + ((size_t)(b * SEQ + qr0 + g)) * DIM + h * HD;
    float* O1 = Out + ((size_t)(b * SEQ + qr0 + g + 8)) * DIM + h * HD;
#pragma unroll
    for (int jn2 = 0; jn2 < 8; jn2++) {
        float2 r0, r1;
        r0.x = __uint_as_float(f2tf32(oacc[jn2][0] * il0));
        r0.y = __uint_as_float(f2tf32(oacc[jn2][1] * il0));
        r1.x = __uint_as_float(f2tf32(oacc[jn2][2] * il1));
        r1.y = __uint_as_float(f2tf32(oacc[jn2][3] * il1));
        *(float2*)&O0[8 * jn2 + 2 * tig] = r0;
        *(float2*)&O1[8 * jn2 + 2 * tig] = r1;
    }
}

// ---------------------------------------------------------------------------
extern "C" void kernel_launch(void* const* d_in, const int* in_sizes, int n_in,
                              void* d_out, int out_size) {
    const float* q  = (const float*)d_in[0];
    const float* k  = (const float*)d_in[1];
    const float* v  = (const float*)d_in[2];
    const int* mask = (const int*)d_in[3];
    const float* Wq = (const float*)d_in[4];
    const float* bq = (const float*)d_in[5];
    const float* Wk = (const float*)d_in[6];
    const float* bk = (const float*)d_in[7];
    const float* Wv = (const float*)d_in[8];
    const float* bv = (const float*)d_in[9];
    const float* Wo = (const float*)d_in[10];
    const float* bo = (const float*)d_in[11];
    float* out = (float*)d_out;

    float *pQ, *pK, *pV, *pA, *pWc, *pXc;
    cudaGetSymbolAddress((void**)&pQ, g_Q);
    cudaGetSymbolAddress((void**)&pK, g_K);
    cudaGetSymbolAddress((void**)&pV, g_V);
    cudaGetSymbolAddress((void**)&pA, g_A);
    cudaGetSymbolAddress((void**)&pWc, g_Wc);
    cudaGetSymbolAddress((void**)&pXc, g_Xc);

    cudaFuncSetAttribute(gemm_qkv, cudaFuncAttributeMaxDynamicSharedMemorySize, SM_GEMM_TOTAL);
    cudaFuncSetAttribute(gemm_out, cudaFuncAttributeMaxDynamicSharedMemorySize, SM_GEMM_TOTAL);
    cudaFuncSetAttribute(flash_attn_tc, cudaFuncAttributeMaxDynamicSharedMemorySize, FLASH_SMEM_BYTES);

    // --- tf32 pre-rounding pre-pass ---
    const int W4 = DIM * DIM / 4;       // 262144
    const int X4 = MROWS * DIM / 4;     // 1048576
    conv_tf32<<<W4 / 256, 256>>>(Wq, pWc + 0 * DIM * DIM, W4);
    conv_tf32<<<W4 / 256, 256>>>(Wk, pWc + 1 * DIM * DIM, W4);
    conv_tf32<<<W4 / 256, 256>>>(Wv, pWc + 2 * DIM * DIM, W4);
    conv_tf32<<<W4 / 256, 256>>>(Wo, pWc + 3 * DIM * DIM, W4);
    conv_tf32<<<X4 / 256, 256>>>(q, pXc + 0 * (size_t)MROWS * DIM, X4);
    conv_tf32<<<X4 / 256, 256>>>(k, pXc + 1 * (size_t)MROWS * DIM, X4);
    conv_tf32<<<X4 / 256, 256>>>(v, pXc + 2 * (size_t)MROWS * DIM, X4);

    GemmArgs aq{pXc + 0 * (size_t)MROWS * DIM, pWc + 0 * DIM * DIM, bq, pQ};
    GemmArgs ak{pXc + 1 * (size_t)MROWS * DIM, pWc + 1 * DIM * DIM, bk, pK};
    GemmArgs av{pXc + 2 * (size_t)MROWS * DIM, pWc + 2 * DIM * DIM, bv, pV};

    dim3 gqkv(DIM / GBN, MROWS / GBM, 3);   // 384 CTAs
    gemm_qkv<<<gqkv, 256, SM_GEMM_TOTAL>>>(aq, ak, av);

    flash_attn_tc<<<dim3(SEQ / 64, NH, BATCH), 128, FLASH_SMEM_BYTES>>>(mask, pA);

    dim3 go(DIM / GBN, MROWS / GBM);        // 128 CTAs
    gemm_out<<<go, 256, SM_GEMM_TOTAL>>>(pA, pWc + 3 * DIM * DIM, bo, out);
}

// round 6
// speedup vs baseline: 7.7232x; 1.6721x over previous
#include <cuda_runtime.h>
#include <cstdint>

// Problem constants
#define BATCH 2
#define SEQ   2048
#define DIM   1024
#define NH    16
#define HD    64
#define MROWS (BATCH * SEQ)   // 4096

// Scratch (allocation-free rule: __device__ globals)
__device__ float g_Q[BATCH * NH * SEQ * HD];   // [b,h,s,hd] (tf32-rounded)
__device__ float g_K[BATCH * NH * SEQ * HD];   // (tf32-rounded)
__device__ float g_V[BATCH * NH * SEQ * HD];   // (tf32-rounded)
__device__ float g_A[BATCH * SEQ * DIM];       // attn out [b,s,h*hd] (tf32-rounded)
__device__ float g_Wc[4 * DIM * DIM];          // tf32-rounded Wq,Wk,Wv,Wo
__device__ float g_Xc[3 * MROWS * DIM];        // tf32-rounded q,k,v

// ---------------------------------------------------------------------------
// Helpers
// ---------------------------------------------------------------------------
__device__ __forceinline__ uint32_t smem_u32(const void* p) {
    uint32_t a;
    asm("{ .reg .u64 t; cvta.to.shared.u64 t, %1; cvt.u32.u64 %0, t; }" : "=r"(a) : "l"(p));
    return a;
}

#define CP_ASYNC16(dst, src) \
    asm volatile("cp.async.cg.shared.global [%0], [%1], 16;" :: "r"(dst), "l"(src))
#define CP_ASYNC4(dst, src) \
    asm volatile("cp.async.ca.shared.global [%0], [%1], 4;" :: "r"(dst), "l"(src))
#define CP_ASYNC_COMMIT() asm volatile("cp.async.commit_group;" ::: "memory")
#define CP_ASYNC_WAIT(n)  asm volatile("cp.async.wait_group %0;" :: "n"(n) : "memory")

__device__ __forceinline__ uint32_t f2tf32(float x) {
    uint32_t r;
    asm("cvt.rna.tf32.f32 %0, %1;" : "=r"(r) : "f"(x));
    return r;
}

#define MMA_TF32(d, av, bv)                                                   \
    asm volatile("mma.sync.aligned.m16n8k8.row.col.f32.tf32.tf32.f32 "        \
                 "{%0,%1,%2,%3}, {%4,%5,%6,%7}, {%8,%9}, {%0,%1,%2,%3};"      \
                 : "+f"((d)[0]), "+f"((d)[1]), "+f"((d)[2]), "+f"((d)[3])     \
                 : "r"((av)[0]), "r"((av)[1]), "r"((av)[2]), "r"((av)[3]),    \
                   "r"((bv)[0]), "r"((bv)[1]))

// Fast exp2 on the FMA pipe. Rel err ~3e-6.
__device__ __forceinline__ float fast_exp2(float x) {
    x = fmaxf(x, -126.0f);
    float t = x + 12582912.0f;            // 2^23 + 2^22
    float i = t - 12582912.0f;
    float f = x - i;
    float p = 1.3333558e-3f;
    p = fmaf(p, f, 9.6181291e-3f);
    p = fmaf(p, f, 5.5504109e-2f);
    p = fmaf(p, f, 2.4022651e-1f);
    p = fmaf(p, f, 6.9314718e-1f);
    p = fmaf(p, f, 1.0f);
    int ib = __float_as_int(t) << 23;     // == i << 23 exactly
    return __int_as_float(__float_as_int(p) + ib);
}

// ---------------------------------------------------------------------------
// One-time tf32 rounding pre-pass. 4 independent float4 per thread (MLP=4).
// ---------------------------------------------------------------------------
__global__ __launch_bounds__(256) void conv_tf32(const float* __restrict__ src,
                                                 float* __restrict__ dst, int n4) {
    int i0 = blockIdx.x * 1024 + threadIdx.x;
    float4 v[4];
    int idx[4];
#pragma unroll
    for (int t = 0; t < 4; t++) {
        idx[t] = i0 + t * 256;
        if (idx[t] < n4) v[t] = ((const float4*)src)[idx[t]];
    }
#pragma unroll
    for (int t = 0; t < 4; t++) {
        if (idx[t] < n4) {
            float4 r;
            r.x = __uint_as_float(f2tf32(v[t].x));
            r.y = __uint_as_float(f2tf32(v[t].y));
            r.z = __uint_as_float(f2tf32(v[t].z));
            r.w = __uint_as_float(f2tf32(v[t].w));
            ((float4*)dst)[idx[t]] = r;
        }
    }
}

// ---------------------------------------------------------------------------
// tf32 mma.sync GEMM: C = A @ W^T + bias. A and W hold pre-rounded tf32 bits.
// CTA tile 128x256, BK=32, 8 warps (2x4), 64x64 each. XOR-swizzled smem.
// ---------------------------------------------------------------------------
#define GBM 128
#define GBN 256
#define GBK 32
#define NKT (DIM / GBK)                 // 32
#define SA_BYTES (GBM * GBK * 4)        // 16384
#define SB_BYTES (GBN * GBK * 4)        // 32768
#define SM_GEMM_TOTAL (2 * (SA_BYTES + SB_BYTES))   // 98304

struct GemmArgs {
    const float* A;
    const float* W;
    const float* bias;
    float* C;
};

template <int SPLIT_HEADS>
__device__ __forceinline__ void gemm_body(const float* __restrict__ A,
                                          const float* __restrict__ W,
                                          const float* __restrict__ bias,
                                          float* __restrict__ C) {
    extern __shared__ char smem[];
    const float* sAf = (const float*)smem;               // [2][128][32]
    const float* sBf = (const float*)(smem + 2 * SA_BYTES);
    const uint32_t sA = smem_u32(smem);
    const uint32_t sB = sA + 2 * SA_BYTES;

    const int tid = threadIdx.x;
    const int lane = tid & 31;
    const int wid = tid >> 5;
    const int wm = wid & 1;
    const int wn = wid >> 1;
    const int g = lane >> 2;
    const int tig = lane & 3;
    const int m0 = blockIdx.y * GBM;
    const int n0 = blockIdx.x * GBN;

    float acc[4][8][4];
#pragma unroll
    for (int i = 0; i < 4; i++)
#pragma unroll
        for (int j = 0; j < 8; j++)
#pragma unroll
            for (int c = 0; c < 4; c++) acc[i][j][c] = 0.f;

    auto stage = [&](int kt, int buf) {
        const int k0 = kt * GBK;
#pragma unroll
        for (int t = 0; t < 4; t++) {
            int idx = tid + t * 256;
            int row = idx >> 3;
            int c = idx & 7;
            uint32_t dst = sA + buf * SA_BYTES + row * 128 + ((c ^ (row & 7)) << 4);
            CP_ASYNC16(dst, &A[(size_t)(m0 + row) * DIM + k0 + c * 4]);
        }
#pragma unroll
        for (int t = 0; t < 8; t++) {
            int idx = tid + t * 256;
            int row = idx >> 3;
            int c = idx & 7;
            uint32_t dst = sB + buf * SB_BYTES + row * 128 + ((c ^ (row & 7)) << 4);
            CP_ASYNC16(dst, &W[(size_t)(n0 + row) * DIM + k0 + c * 4]);
        }
    };

    stage(0, 0);
    CP_ASYNC_COMMIT();

    for (int kt = 0; kt < NKT; kt++) {
        if (kt + 1 < NKT) {
            stage(kt + 1, (kt + 1) & 1);
            CP_ASYNC_COMMIT();
            CP_ASYNC_WAIT(1);
        } else {
            CP_ASYNC_WAIT(0);
        }
        __syncthreads();

        const float* Ab = sAf + (kt & 1) * (SA_BYTES / 4);
        const float* Bb = sBf + (kt & 1) * (SB_BYTES / 4);
#pragma unroll
        for (int s = 0; s < 4; s++) {
            const int k1 = s * 8 + tig;
            const int k2 = k1 + 4;
            uint32_t a[4][4];
#pragma unroll
            for (int i = 0; i < 4; i++) {
                int r1 = wm * 64 + i * 16 + g;
                int r2 = r1 + 8;
                a[i][0] = __float_as_uint(Ab[r1 * 32 + (k1 ^ ((r1 & 7) << 2))]);
                a[i][1] = __float_as_uint(Ab[r2 * 32 + (k1 ^ ((r2 & 7) << 2))]);
                a[i][2] = __float_as_uint(Ab[r1 * 32 + (k2 ^ ((r1 & 7) << 2))]);
                a[i][3] = __float_as_uint(Ab[r2 * 32 + (k2 ^ ((r2 & 7) << 2))]);
            }
            uint32_t bf[8][2];
#pragma unroll
            for (int j = 0; j < 8; j++) {
                int rn = wn * 64 + j * 8 + g;
                bf[j][0] = __float_as_uint(Bb[rn * 32 + (k1 ^ ((rn & 7) << 2))]);
                bf[j][1] = __float_as_uint(Bb[rn * 32 + (k2 ^ ((rn & 7) << 2))]);
            }
#pragma unroll
            for (int i = 0; i < 4; i++)
#pragma unroll
                for (int j = 0; j < 8; j++) MMA_TF32(acc[i][j], a[i], bf[j]);
        }
        __syncthreads();
    }

#pragma unroll
    for (int i = 0; i < 4; i++) {
        const int m1 = m0 + wm * 64 + i * 16 + g;
        const int m2 = m1 + 8;
#pragma unroll
        for (int j = 0; j < 8; j++) {
            const int n = n0 + wn * 64 + j * 8 + tig * 2;
            const float2 bb = *(const float2*)&bias[n];
            float2 r1, r2;
            if (SPLIT_HEADS) {
                r1.x = __uint_as_float(f2tf32(acc[i][j][0] + bb.x));
                r1.y = __uint_as_float(f2tf32(acc[i][j][1] + bb.y));
                r2.x = __uint_as_float(f2tf32(acc[i][j][2] + bb.x));
                r2.y = __uint_as_float(f2tf32(acc[i][j][3] + bb.y));
                int h = n >> 6;
                int hd = n & (HD - 1);
                {
                    int b = m1 >> 11, sq = m1 & (SEQ - 1);
                    *(float2*)&C[((size_t)((b * NH + h) * SEQ + sq)) * HD + hd] = r1;
                }
                {
                    int b = m2 >> 11, sq = m2 & (SEQ - 1);
                    *(float2*)&C[((size_t)((b * NH + h) * SEQ + sq)) * HD + hd] = r2;
                }
            } else {
                r1.x = acc[i][j][0] + bb.x;
                r1.y = acc[i][j][1] + bb.y;
                r2.x = acc[i][j][2] + bb.x;
                r2.y = acc[i][j][3] + bb.y;
                *(float2*)&C[(size_t)m1 * DIM + n] = r1;
                *(float2*)&C[(size_t)m2 * DIM + n] = r2;
            }
        }
    }
}

__global__ __launch_bounds__(256, 1) void gemm_qkv(GemmArgs a0, GemmArgs a1, GemmArgs a2) {
    const GemmArgs& a = (blockIdx.z == 0) ? a0 : (blockIdx.z == 1) ? a1 : a2;
    gemm_body<1>(a.A, a.W, a.bias, a.C);
}

__global__ __launch_bounds__(256, 1) void gemm_out(const float* __restrict__ A,
                                                   const float* __restrict__ W,
                                                   const float* __restrict__ bias,
                                                   float* __restrict__ C) {
    gemm_body<0>(A, W, bias, C);
}

// ---------------------------------------------------------------------------
// Tensor-core flash attention (tf32 mma.sync), M=32 rows per warp.
// 128 thr (4 warps) = 128 q-rows/CTA; each K/V fragment feeds 2 MMAs.
// smem 111KB -> 2 CTAs/SM. KV double-buffered via cp.async.
// ---------------------------------------------------------------------------
#define FKT 64
#define KVS 72          // smem row stride (floats)
#define FNT (SEQ / FKT) // 32

#define F_KSM 0
#define F_VSM (2 * FKT * KVS)                 // 9216
#define F_PSM (F_VSM + 2 * FKT * KVS)         // 18432
#define F_MSK (F_PSM + 128 * KVS)             // 27648 (int region)
#define F_TOTAL_FLOATS (F_MSK + 2 * FKT)      // 27776
#define FLASH_SMEM_BYTES (F_TOTAL_FLOATS * 4) // 111104

#define CS 0.18033688f  // 0.125 * log2(e)

__global__ __launch_bounds__(128) void flash_attn_tc(const int* __restrict__ mask,
                                                     float* __restrict__ Out) {
    extern __shared__ char smem[];
    float* smf = (float*)smem;
    int* smi = (int*)smem;
    const uint32_t sbase = smem_u32(smem);

    const int b = blockIdx.z;
    const int h = blockIdx.y;
    const int tid = threadIdx.x;
    const int w = tid >> 5;
    const int lane = tid & 31;
    const int g = lane >> 2;       // 0..7
    const int tig = lane & 3;      // 0..3
    const int qr0 = blockIdx.x * 128 + w * 32;

    const float* Qp = g_Q + ((size_t)((b * NH + h) * SEQ) + qr0) * HD;
    const float* Kb = g_K + ((size_t)((b * NH + h) * SEQ)) * HD;
    const float* Vb = g_V + ((size_t)((b * NH + h) * SEQ)) * HD;
    const int* mb = mask + b * SEQ;

    // Persistent Q A-fragments for two 16-row m-tiles (pre-rounded tf32 bits)
    uint32_t aQ[2][8][4];
#pragma unroll
    for (int mi = 0; mi < 2; mi++) {
        const float* Qm = Qp + (size_t)(16 * mi) * HD;
#pragma unroll
        for (int s = 0; s < 8; s++) {
            aQ[mi][s][0] = __float_as_uint(Qm[g * HD + 8 * s + tig]);
            aQ[mi][s][1] = __float_as_uint(Qm[(g + 8) * HD + 8 * s + tig]);
            aQ[mi][s][2] = __float_as_uint(Qm[g * HD + 8 * s + tig + 4]);
            aQ[mi][s][3] = __float_as_uint(Qm[(g + 8) * HD + 8 * s + tig + 4]);
        }
    }

    float oacc[2][8][4];
#pragma unroll
    for (int mi = 0; mi < 2; mi++)
#pragma unroll
        for (int j = 0; j < 8; j++)
#pragma unroll
            for (int c = 0; c < 4; c++) oacc[mi][j][c] = 0.f;
    float mrun[4] = {-1e30f, -1e30f, -1e30f, -1e30f};  // rows g, g+8 per mi
    float lrun[4] = {0.f, 0.f, 0.f, 0.f};

    auto stage = [&](int kt, int buf) {
        const float* Kg = Kb + (size_t)kt * FKT * HD;
        const float* Vg = Vb + (size_t)kt * FKT * HD;
        const uint32_t dK = sbase + (F_KSM + buf * FKT * KVS) * 4;
        const uint32_t dV = sbase + (F_VSM + buf * FKT * KVS) * 4;
#pragma unroll
        for (int t = 0; t < 8; t++) {
            int idx = tid + t * 128;       // 0..1023
            int row = idx >> 4;
            int c = idx & 15;
            CP_ASYNC16(dK + row * (KVS * 4) + c * 16, &Kg[row * HD + c * 4]);
            CP_ASYNC16(dV + row * (KVS * 4) + c * 16, &Vg[row * HD + c * 4]);
        }
        if (tid < FKT) {
            CP_ASYNC4(sbase + (F_MSK + buf * FKT + tid) * 4, &mb[kt * FKT + tid]);
        }
    };

    stage(0, 0);
    CP_ASYNC_COMMIT();

    uint32_t* Pw = (uint32_t*)(smf + F_PSM + w * 32 * KVS);

    for (int kt = 0; kt < FNT; kt++) {
        if (kt + 1 < FNT) {
            stage(kt + 1, (kt + 1) & 1);
            CP_ASYNC_COMMIT();
            CP_ASYNC_WAIT(1);
        } else {
            CP_ASYNC_WAIT(0);
        }
        __syncthreads();

        const int buf = kt & 1;
        const float* Kbuf = smf + F_KSM + buf * FKT * KVS;
        const float* Vbuf = smf + F_VSM + buf * FKT * KVS;
        const int* mk = smi + F_MSK + buf * FKT;

        // ---- S = Q @ K^T (32 x 64 per warp); each K frag feeds 2 MMAs ----
        float sc[2][8][4];
#pragma unroll
        for (int mi = 0; mi < 2; mi++)
#pragma unroll
            for (int j = 0; j < 8; j++)
#pragma unroll
                for (int c = 0; c < 4; c++) sc[mi][j][c] = 0.f;
#pragma unroll
        for (int s = 0; s < 8; s++) {
#pragma unroll
            for (int jn = 0; jn < 8; jn++) {
                uint32_t bf[2];
                bf[0] = __float_as_uint(Kbuf[(8 * jn + g) * KVS + 8 * s + tig]);
                bf[1] = __float_as_uint(Kbuf[(8 * jn + g) * KVS + 8 * s + tig + 4]);
                MMA_TF32(sc[0][jn], aQ[0][s], bf);
                MMA_TF32(sc[1][jn], aQ[1][s], bf);
            }
        }

        // ---- online softmax (log2 domain), per m-tile ----
#pragma unroll
        for (int mi = 0; mi < 2; mi++) {
#pragma unroll
            for (int jn = 0; jn < 8; jn++) {
                int2 mv = *(const int2*)&mk[8 * jn + 2 * tig];
                float ax = mv.x ? -1e30f : 0.f;
                float ay = mv.y ? -1e30f : 0.f;
                sc[mi][jn][0] = fmaf(sc[mi][jn][0], CS, ax);
                sc[mi][jn][1] = fmaf(sc[mi][jn][1], CS, ay);
                sc[mi][jn][2] = fmaf(sc[mi][jn][2], CS, ax);
                sc[mi][jn][3] = fmaf(sc[mi][jn][3], CS, ay);
            }
            float mx0 = -1e30f, mx1 = -1e30f;
#pragma unroll
            for (int jn = 0; jn < 8; jn++) {
                mx0 = fmaxf(mx0, fmaxf(sc[mi][jn][0], sc[mi][jn][1]));
                mx1 = fmaxf(mx1, fmaxf(sc[mi][jn][2], sc[mi][jn][3]));
            }
            mx0 = fmaxf(mx0, __shfl_xor_sync(0xFFFFFFFF, mx0, 1));
            mx0 = fmaxf(mx0, __shfl_xor_sync(0xFFFFFFFF, mx0, 2));
            mx1 = fmaxf(mx1, __shfl_xor_sync(0xFFFFFFFF, mx1, 1));
            mx1 = fmaxf(mx1, __shfl_xor_sync(0xFFFFFFFF, mx1, 2));

            const float nm0 = fmaxf(mrun[2 * mi], mx0);
            const float nm1 = fmaxf(mrun[2 * mi + 1], mx1);
            const float cor0 = fast_exp2(mrun[2 * mi] - nm0);
            const float cor1 = fast_exp2(mrun[2 * mi + 1] - nm1);
            mrun[2 * mi] = nm0;
            mrun[2 * mi + 1] = nm1;

            float s0 = 0.f, s1 = 0.f;
#pragma unroll
            for (int jn = 0; jn < 8; jn++) {
                sc[mi][jn][0] = fast_exp2(sc[mi][jn][0] - nm0);
                sc[mi][jn][1] = fast_exp2(sc[mi][jn][1] - nm0);
                sc[mi][jn][2] = fast_exp2(sc[mi][jn][2] - nm1);
                sc[mi][jn][3] = fast_exp2(sc[mi][jn][3] - nm1);
                s0 += sc[mi][jn][0] + sc[mi][jn][1];
                s1 += sc[mi][jn][2] + sc[mi][jn][3];
            }
            s0 += __shfl_xor_sync(0xFFFFFFFF, s0, 1);
            s0 += __shfl_xor_sync(0xFFFFFFFF, s0, 2);
            s1 += __shfl_xor_sync(0xFFFFFFFF, s1, 1);
            s1 += __shfl_xor_sync(0xFFFFFFFF, s1, 2);
            lrun[2 * mi] = lrun[2 * mi] * cor0 + s0;
            lrun[2 * mi + 1] = lrun[2 * mi + 1] * cor1 + s1;

#pragma unroll
            for (int j = 0; j < 8; j++) {
                oacc[mi][j][0] *= cor0;
                oacc[mi][j][1] *= cor0;
                oacc[mi][j][2] *= cor1;
                oacc[mi][j][3] *= cor1;
            }

            // P -> smem (tf32 bits), rows 16*mi + {g, g+8}
#pragma unroll
            for (int jn = 0; jn < 8; jn++) {
                Pw[(16 * mi + g) * KVS + 8 * jn + 2 * tig]           = f2tf32(sc[mi][jn][0]);
                Pw[(16 * mi + g) * KVS + 8 * jn + 2 * tig + 1]       = f2tf32(sc[mi][jn][1]);
                Pw[(16 * mi + g + 8) * KVS + 8 * jn + 2 * tig]       = f2tf32(sc[mi][jn][2]);
                Pw[(16 * mi + g + 8) * KVS + 8 * jn + 2 * tig + 1]   = f2tf32(sc[mi][jn][3]);
            }
        }
        __syncwarp();

        // ---- O += P @ V; each V frag feeds 2 MMAs ----
#pragma unroll
        for (int s2 = 0; s2 < 8; s2++) {
            uint32_t pa0[4], pa1[4];
            pa0[0] = Pw[g * KVS + 8 * s2 + tig];
            pa0[1] = Pw[(g + 8) * KVS + 8 * s2 + tig];
            pa0[2] = Pw[g * KVS + 8 * s2 + tig + 4];
            pa0[3] = Pw[(g + 8) * KVS + 8 * s2 + tig + 4];
            pa1[0] = Pw[(g + 16) * KVS + 8 * s2 + tig];
            pa1[1] = Pw[(g + 24) * KVS + 8 * s2 + tig];
            pa1[2] = Pw[(g + 16) * KVS + 8 * s2 + tig + 4];
            pa1[3] = Pw[(g + 24) * KVS + 8 * s2 + tig + 4];
#pragma unroll
            for (int jn2 = 0; jn2 < 8; jn2++) {
                uint32_t bf[2];
                bf[0] = __float_as_uint(Vbuf[(8 * s2 + tig) * KVS + 8 * jn2 + g]);
                bf[1] = __float_as_uint(Vbuf[(8 * s2 + tig + 4) * KVS + 8 * jn2 + g]);
                MMA_TF32(oacc[0][jn2], pa0, bf);
                MMA_TF32(oacc[1][jn2], pa1, bf);
            }
        }
        __syncthreads();   // all warps done with buf before restage
    }

    // ---- epilogue: normalize + store tf32-rounded to g_A ----
#pragma unroll
    for (int mi = 0; mi < 2; mi++) {
        const float il0 = 1.f / lrun[2 * mi];
        const float il1 = 1.f / lrun[2 * mi + 1];
        float* O0 = Out + ((size_t)(b * SEQ + qr0 + 16 * mi + g)) * DIM + h * HD;
        float* O1 = Out + ((size_t)(b * SEQ + qr0 + 16 * mi + g + 8)) * DIM + h * HD;
#pragma unroll
        for (int jn2 = 0; jn2 < 8; jn2++) {
            float2 r0, r1;
            r0.x = __uint_as_float(f2tf32(oacc[mi][jn2][0] * il0));
            r0.y = __uint_as_float(f2tf32(oacc[mi][jn2][1] * il0));
            r1.x = __uint_as_float(f2tf32(oacc[mi][jn2][2] * il1));
            r1.y = __uint_as_float(f2tf32(oacc[mi][jn2][3] * il1));
            *(float2*)&O0[8 * jn2 + 2 * tig] = r0;
            *(float2*)&O1[8 * jn2 + 2 * tig] = r1;
        }
    }
}

// ---------------------------------------------------------------------------
extern "C" void kernel_launch(void* const* d_in, const int* in_sizes, int n_in,
                              void* d_out, int out_size) {
    const float* q  = (const float*)d_in[0];
    const float* k  = (const float*)d_in[1];
    const float* v  = (const float*)d_in[2];
    const int* mask = (const int*)d_in[3];
    const float* Wq = (const float*)d_in[4];
    const float* bq = (const float*)d_in[5];
    const float* Wk = (const float*)d_in[6];
    const float* bk = (const float*)d_in[7];
    const float* Wv = (const float*)d_in[8];
    const float* bv = (const float*)d_in[9];
    const float* Wo = (const float*)d_in[10];
    const float* bo = (const float*)d_in[11];
    float* out = (float*)d_out;

    float *pQ, *pK, *pV, *pA, *pWc, *pXc;
    cudaGetSymbolAddress((void**)&pQ, g_Q);
    cudaGetSymbolAddress((void**)&pK, g_K);
    cudaGetSymbolAddress((void**)&pV, g_V);
    cudaGetSymbolAddress((void**)&pA, g_A);
    cudaGetSymbolAddress((void**)&pWc, g_Wc);
    cudaGetSymbolAddress((void**)&pXc, g_Xc);

    cudaFuncSetAttribute(gemm_qkv, cudaFuncAttributeMaxDynamicSharedMemorySize, SM_GEMM_TOTAL);
    cudaFuncSetAttribute(gemm_out, cudaFuncAttributeMaxDynamicSharedMemorySize, SM_GEMM_TOTAL);
    cudaFuncSetAttribute(flash_attn_tc, cudaFuncAttributeMaxDynamicSharedMemorySize, FLASH_SMEM_BYTES);

    // --- tf32 pre-rounding pre-pass (MLP=4 per thread) ---
    const int W4 = DIM * DIM / 4;       // 262144
    const int X4 = MROWS * DIM / 4;     // 1048576
    conv_tf32<<<W4 / 1024, 256>>>(Wq, pWc + 0 * DIM * DIM, W4);
    conv_tf32<<<W4 / 1024, 256>>>(Wk, pWc + 1 * DIM * DIM, W4);
    conv_tf32<<<W4 / 1024, 256>>>(Wv, pWc + 2 * DIM * DIM, W4);
    conv_tf32<<<W4 / 1024, 256>>>(Wo, pWc + 3 * DIM * DIM, W4);
    conv_tf32<<<X4 / 1024, 256>>>(q, pXc + 0 * (size_t)MROWS * DIM, X4);
    conv_tf32<<<X4 / 1024, 256>>>(k, pXc + 1 * (size_t)MROWS * DIM, X4);
    conv_tf32<<<X4 / 1024, 256>>>(v, pXc + 2 * (size_t)MROWS * DIM, X4);

    GemmArgs aq{pXc + 0 * (size_t)MROWS * DIM, pWc + 0 * DIM * DIM, bq, pQ};
    GemmArgs ak{pXc + 1 * (size_t)MROWS * DIM, pWc + 1 * DIM * DIM, bk, pK};
    GemmArgs av{pXc + 2 * (size_t)MROWS * DIM, pWc + 2 * DIM * DIM, bv, pV};

    dim3 gqkv(DIM / GBN, MROWS / GBM, 3);   // 384 CTAs
    gemm_qkv<<<gqkv, 256, SM_GEMM_TOTAL>>>(aq, ak, av);

    flash_attn_tc<<<dim3(SEQ / 128, NH, BATCH), 128, FLASH_SMEM_BYTES>>>(mask, pA);

    dim3 go(DIM / GBN, MROWS / GBM);        // 128 CTAs
    gemm_out<<<go, 256, SM_GEMM_TOTAL>>>(pA, pWc + 3 * DIM * DIM, bo, out);
}